// round 1
// baseline (speedup 1.0000x reference)
#include <cuda_runtime.h>

// GeneralMechanismODE: ordered bi-bi mechanism, 8 species, 4 reversible
// transitions, all index tables compile-time constant.
//
// Per row b:
//   vf0 = kf0 * y0 * y4   (E  + A -> EA)
//   vf1 = kf1 * y1 * y5   (EA + B -> EAB)
//   vf2 = kf2 * y3        (EAB    -> EQ + P)
//   vf3 = kf3 * y2        (EQ     -> E  + Q)
//   vr0 = kr0 * y1
//   vr1 = kr1 * y3
//   vr2 = kr2 * y2 * y6
//   vr3 = kr3 * y0 * y7
//   v_i = vf_i - vr_i
// Stoichiometry (fixed):
//   dy0 = -v0 + v3 ; dy1 = v0 - v1 ; dy2 = v2 - v3 ; dy3 = v1 - v2
//   dy4 = -v0 ; dy5 = -v1 ; dy6 = v2 ; dy7 = v3

__global__ __launch_bounds__(256) void ode_kernel(
    const float4* __restrict__ y,    // B rows x 8 floats = 2 x float4 per row
    const float4* __restrict__ kf,   // B rows x 4 floats = 1 x float4 per row
    const float4* __restrict__ kr,   // B rows x 4 floats = 1 x float4 per row
    float4* __restrict__ out,        // B rows x 8 floats = 2 x float4 per row
    int B)
{
    int b = blockIdx.x * blockDim.x + threadIdx.x;
    if (b >= B) return;

    // Issue all 4 independent 128-bit loads up front (MLP=4).
    float4 ylo = y[2 * b + 0];   // y0..y3
    float4 yhi = y[2 * b + 1];   // y4..y7
    float4 f   = kf[b];
    float4 r   = kr[b];

    float v0 = f.x * ylo.x * yhi.x - r.x * ylo.y;          // kf0*E*A  - kr0*EA
    float v1 = f.y * ylo.y * yhi.y - r.y * ylo.w;          // kf1*EA*B - kr1*EAB
    float v2 = f.z * ylo.w         - r.z * ylo.z * yhi.z;  // kf2*EAB  - kr2*EQ*P
    float v3 = f.w * ylo.z         - r.w * ylo.x * yhi.w;  // kf3*EQ   - kr3*E*Q

    float4 olo, ohi;
    olo.x = v3 - v0;   // dE
    olo.y = v0 - v1;   // dEA
    olo.z = v2 - v3;   // dEQ
    olo.w = v1 - v2;   // dEAB
    ohi.x = -v0;       // dA
    ohi.y = -v1;       // dB
    ohi.z = v2;        // dP
    ohi.w = v3;        // dQ

    out[2 * b + 0] = olo;
    out[2 * b + 1] = ohi;
}

extern "C" void kernel_launch(void* const* d_in, const int* in_sizes, int n_in,
                              void* d_out, int out_size)
{
    // metadata order: t (1), y (B*8), forward_rates (B*4), reverse_rates (B*4)
    const float4* y  = (const float4*)d_in[1];
    const float4* kf = (const float4*)d_in[2];
    const float4* kr = (const float4*)d_in[3];
    float4* out = (float4*)d_out;

    int B = in_sizes[1] / 8;
    int threads = 256;
    int blocks = (B + threads - 1) / threads;
    ode_kernel<<<blocks, threads>>>(y, kf, kr, out, B);
}